// round 7
// baseline (speedup 1.0000x reference)
#include <cuda_runtime.h>
#include <cstdint>

#define BATCH    4194304u
#define EPT      4u                         // elements per thread
#define INV_LN2  1.4426950408889634f
// vbits = (bits>>9)|0x3f800000 ; patch when u > ~0.99930 (t too small for MUFU.LG2)
#define VPATCH   (0x3f800000u | 8382700u)

// Packed tables: lp[6] = log_softmax(W.T+b) by (card*3+action); wn[6] = -exp(-lp)
// argmax_a lp_a - ln(-ln u_a)  ==  argmin_a  lg2(u_a) * wn_a   (exact monotone map)
struct __align__(16) Tbl { float4 a, b, c; };
__device__ Tbl d_tbl;

__global__ void init_logp_kernel(const float* __restrict__ W,
                                 const float* __restrict__ bias) {
    if (threadIdx.x == 0 && blockIdx.x == 0) {
        float lp[6], wn[6];
        #pragma unroll
        for (int c = 0; c < 2; c++) {
            // W is (3,2) row-major; x_a = W[a,c] + b[a]
            float x0 = W[0 * 2 + c] + bias[0];
            float x1 = W[1 * 2 + c] + bias[1];
            float x2 = W[2 * 2 + c] + bias[2];
            float m  = fmaxf(x0, fmaxf(x1, x2));
            float s0 = x0 - m, s1 = x1 - m, s2 = x2 - m;
            float l  = logf(expf(s0) + expf(s1) + expf(s2));
            lp[c*3+0] = s0 - l;  lp[c*3+1] = s1 - l;  lp[c*3+2] = s2 - l;
            #pragma unroll
            for (int a = 0; a < 3; a++) wn[c*3+a] = -expf(-lp[c*3+a]);
        }
        Tbl t;
        t.a = make_float4(lp[0], lp[1], lp[2], lp[3]);
        t.b = make_float4(lp[4], lp[5], wn[0], wn[1]);
        t.c = make_float4(wn[2], wn[3], wn[4], wn[5]);
        d_tbl = t;
    }
}

// JAX partitionable-threefry 32-bit draw for global element index i (< 2^32):
//   (o0, o1) = threefry2x32(key=(0,42), x0=hi32(i)=0, x1=lo32(i)=i); bits = o0 ^ o1
__device__ __forceinline__ uint32_t tf_bits(uint32_t ctr) {
    const uint32_t k1 = 42u;
    const uint32_t k2 = 42u ^ 0x1BD11BDAu;
    uint32_t x0 = 0u;            // hi32 + k0 = 0
    uint32_t x1 = ctr + 42u;
#define TF_RND(r) { x0 += x1; x1 = __funnelshift_l(x1, x1, (r)); x1 ^= x0; }
    TF_RND(13) TF_RND(15) TF_RND(26) TF_RND(6)
    x0 += k1; x1 += k2 + 1u;
    TF_RND(17) TF_RND(29) TF_RND(16) TF_RND(24)
    x0 += k2; x1 += 2u;
    TF_RND(13) TF_RND(15) TF_RND(26) TF_RND(6)
    x1 += k1 + 3u;               // x0 += k0 folds away
    TF_RND(17) TF_RND(29) TF_RND(16) TF_RND(24)
    x0 += k1; x1 += k2 + 4u;
    TF_RND(13) TF_RND(15) TF_RND(26) TF_RND(6)
    x0 += k2; x1 += 5u;
#undef TF_RND
    return x0 ^ x1;
}

__global__ void __launch_bounds__(256)
sample_kernel(const int* __restrict__ cards, float* __restrict__ out) {
    uint32_t e0 = (blockIdx.x * 256u + threadIdx.x) * EPT;  // grid divides exactly

    int4 cards4 = *reinterpret_cast<const int4*>(cards + e0);
    int  cardv[4] = {cards4.x, cards4.y, cards4.z, cards4.w};

    Tbl tb = d_tbl;                                          // 3x LDG.128
    float lp[6] = {tb.a.x, tb.a.y, tb.a.z, tb.a.w, tb.b.x, tb.b.y};
    float wn[6] = {tb.b.z, tb.b.w, tb.c.x, tb.c.y, tb.c.z, tb.c.w};

    float4 u0q;
    float4 belq[2];
    float4 lcfq[2];
    float* u0p  = &u0q.x;
    float* belp = &belq[0].x;
    float* lcfp = &lcfq[0].x;

    #pragma unroll
    for (uint32_t e = 0; e < EPT; e++) {
        uint32_t base = (e0 + e) * 6u;

        // 6 independent threefry chains (ILP), then uniform bits in one funnel-shift:
        // vbits = (o>>9) | 0x3f800000 ; u = as_float(vbits) - 1  (exact)
        uint32_t vb[6];
        float    u[6], L[6];
        #pragma unroll
        for (int j = 0; j < 6; j++) {
            uint32_t o = tf_bits(base + (uint32_t)j);
            vb[j] = __funnelshift_r(o, 0x7Fu, 9);
            u[j]  = __uint_as_float(vb[j]) - 1.0f;
            L[j]  = __log2f(u[j]);                 // MUFU.LG2, abs err ~2^-22
        }
        // Patch near-1 draws (|lg2 u| < ~1e-3) with precise log: rel err ~2e-7.
        #pragma unroll
        for (int j = 0; j < 6; j++)
            if (vb[j] > VPATCH) L[j] = logf(u[j]) * INV_LN2;

        int   cf[2];
        float lcf[2];
        bool  need_exact = false;
        #pragma unroll
        for (int c = 0; c < 2; c++) {
            float p0 = L[c*3+0] * wn[c*3+0];       // positive; argmin == ref argmax
            float p1 = L[c*3+1] * wn[c*3+1];
            float p2 = L[c*3+2] * wn[c*3+2];
            int   bi = 0;
            float best = p0;
            if (p1 < best) { best = p1; bi = 1; }
            if (p2 < best) { best = p2; bi = 2; }
            float second = fmaxf(fminf(p0, p1), fminf(fmaxf(p0, p1), p2));
            // fast rel err <= ~2.4e-4; eps = 1e-3 (4x margin)
            need_exact |= (second < fmaf(best, 1e-3f, best));
            cf[c]  = bi;
            lcf[c] = lp[c*3 + bi];
        }

        if (need_exact) {
            // Bit-exact reference arithmetic: s = lp - log(-log(max(u, tiny)))
            #pragma unroll
            for (int c = 0; c < 2; c++) {
                int   bi   = 0;
                float best = -1e30f;
                #pragma unroll
                for (int a = 0; a < 3; a++) {
                    float uc = fmaxf(u[c*3+a], 1.17549435e-38f);
                    float s  = lp[c*3+a] - logf(-logf(uc));
                    if (s > best) { best = s; bi = a; }   // first-max tie rule
                }
                cf[c]  = bi;
                lcf[c] = lp[c*3 + bi];
            }
        }

        int card = cardv[e];                       // in {0,1}
        int u0i  = (card == 0) ? cf[0] : cf[1];
        u0p[e]   = (float)u0i;

        bool eq = (cf[0] == cf[1]);
        belp[e*2 + 0] = eq ? 0.5f : ((card == 0) ? 1.0f : 0.0f);
        belp[e*2 + 1] = eq ? 0.5f : ((card == 0) ? 0.0f : 1.0f);
        lcfp[e*2 + 0] = lcf[0];
        lcfp[e*2 + 1] = lcf[1];
    }

    // Vectorized stores: out = [u0(B) | beliefs(B,2) | log_cf(B,2)]
    *reinterpret_cast<float4*>(out + e0)                          = u0q;
    float* bel_base = out + BATCH + 2u * e0;
    reinterpret_cast<float4*>(bel_base)[0]                        = belq[0];
    reinterpret_cast<float4*>(bel_base)[1]                        = belq[1];
    float* lcf_base = out + 3 * (size_t)BATCH + 2u * e0;
    reinterpret_cast<float4*>(lcf_base)[0]                        = lcfq[0];
    reinterpret_cast<float4*>(lcf_base)[1]                        = lcfq[1];
}

extern "C" void kernel_launch(void* const* d_in, const int* in_sizes, int n_in,
                              void* d_out, int out_size) {
    const int*   cards = (const int*)d_in[0];     // cards_0: (B,) int32
    const float* W     = (const float*)d_in[1];   // (3,2) float32
    const float* bias  = (const float*)d_in[2];   // (3,) float32
    float*       out   = (float*)d_out;           // [u0(B) | beliefs(B,2) | log_cf(B,2)]

    init_logp_kernel<<<1, 32>>>(W, bias);
    sample_kernel<<<BATCH / (256 * EPT), 256>>>(cards, out);
}

// round 8
// speedup vs baseline: 1.1200x; 1.1200x over previous
#include <cuda_runtime.h>
#include <cstdint>

#define BATCH    4194304u
#define EPT      2u                         // elements per thread
#define INV_LN2  1.4426950408889634f
// vbits = (bits>>9)|0x3f800000 ; patch when u > ~0.99930 (t too small for MUFU.LG2)
#define VPATCH   (0x3f800000u | 8382700u)

// Packed tables: lp[6] = log_softmax(W.T+b) by (card*3+action); wn[6] = -exp(-lp)
// argmax_a lp_a - ln(-ln u_a)  ==  argmin_a  lg2(u_a) * wn_a   (exact monotone map)
struct __align__(16) Tbl { float4 a, b, c; };
__device__ Tbl d_tbl;

__global__ void init_logp_kernel(const float* __restrict__ W,
                                 const float* __restrict__ bias) {
    if (threadIdx.x == 0 && blockIdx.x == 0) {
        float lp[6], wn[6];
        #pragma unroll
        for (int c = 0; c < 2; c++) {
            // W is (3,2) row-major; x_a = W[a,c] + b[a]
            float x0 = W[0 * 2 + c] + bias[0];
            float x1 = W[1 * 2 + c] + bias[1];
            float x2 = W[2 * 2 + c] + bias[2];
            float m  = fmaxf(x0, fmaxf(x1, x2));
            float s0 = x0 - m, s1 = x1 - m, s2 = x2 - m;
            float l  = logf(expf(s0) + expf(s1) + expf(s2));
            lp[c*3+0] = s0 - l;  lp[c*3+1] = s1 - l;  lp[c*3+2] = s2 - l;
            #pragma unroll
            for (int a = 0; a < 3; a++) wn[c*3+a] = -expf(-lp[c*3+a]);
        }
        Tbl t;
        t.a = make_float4(lp[0], lp[1], lp[2], lp[3]);
        t.b = make_float4(lp[4], lp[5], wn[0], wn[1]);
        t.c = make_float4(wn[2], wn[3], wn[4], wn[5]);
        d_tbl = t;
    }
}

// JAX partitionable-threefry 32-bit draw for global element index i (< 2^32):
//   (o0, o1) = threefry2x32(key=(0,42), x0=hi32(i)=0, x1=lo32(i)=i); bits = o0 ^ o1
__device__ __forceinline__ uint32_t tf_bits(uint32_t ctr) {
    const uint32_t k1 = 42u;
    const uint32_t k2 = 42u ^ 0x1BD11BDAu;
    uint32_t x0 = 0u;            // hi32 + k0 = 0
    uint32_t x1 = ctr + 42u;
#define TF_RND(r) { x0 += x1; x1 = __funnelshift_l(x1, x1, (r)); x1 ^= x0; }
    TF_RND(13) TF_RND(15) TF_RND(26) TF_RND(6)
    x0 += k1; x1 += k2 + 1u;
    TF_RND(17) TF_RND(29) TF_RND(16) TF_RND(24)
    x0 += k2; x1 += 2u;
    TF_RND(13) TF_RND(15) TF_RND(26) TF_RND(6)
    x1 += k1 + 3u;               // x0 += k0 folds away
    TF_RND(17) TF_RND(29) TF_RND(16) TF_RND(24)
    x0 += k1; x1 += k2 + 4u;
    TF_RND(13) TF_RND(15) TF_RND(26) TF_RND(6)
    x0 += k2; x1 += 5u;
#undef TF_RND
    return x0 ^ x1;
}

__global__ void __launch_bounds__(256)
sample_kernel(const int* __restrict__ cards, float* __restrict__ out) {
    uint32_t e0 = (blockIdx.x * 256u + threadIdx.x) * EPT;  // grid divides exactly

    int2 cards2 = *reinterpret_cast<const int2*>(cards + e0);
    int  cardv[2] = {cards2.x, cards2.y};

    Tbl tb = d_tbl;                                          // 3x LDG.128
    float lp[6] = {tb.a.x, tb.a.y, tb.a.z, tb.a.w, tb.b.x, tb.b.y};
    float wn[6] = {tb.b.z, tb.b.w, tb.c.x, tb.c.y, tb.c.z, tb.c.w};

    float2 u0d;
    float4 belq;
    float4 lcfq;
    float* u0p  = &u0d.x;
    float* belp = &belq.x;
    float* lcfp = &lcfq.x;

    #pragma unroll
    for (uint32_t e = 0; e < EPT; e++) {
        uint32_t base = (e0 + e) * 6u;

        // 6 independent threefry chains (ILP), then uniform bits in one funnel-shift:
        // vbits = (o>>9) | 0x3f800000 ; u = as_float(vbits) - 1  (exact)
        uint32_t vb[6];
        float    u[6], L[6];
        #pragma unroll
        for (int j = 0; j < 6; j++) {
            uint32_t o = tf_bits(base + (uint32_t)j);
            vb[j] = __funnelshift_r(o, 0x7Fu, 9);
            u[j]  = __uint_as_float(vb[j]) - 1.0f;
            L[j]  = __log2f(u[j]);                 // MUFU.LG2, abs err ~2^-22
        }
        // Patch near-1 draws (|lg2 u| < ~1e-3) with precise log: rel err ~2e-7.
        #pragma unroll
        for (int j = 0; j < 6; j++)
            if (vb[j] > VPATCH) L[j] = logf(u[j]) * INV_LN2;

        int   cf[2];
        float lcf[2];
        bool  need_exact = false;
        #pragma unroll
        for (int c = 0; c < 2; c++) {
            float p0 = L[c*3+0] * wn[c*3+0];       // positive; argmin == ref argmax
            float p1 = L[c*3+1] * wn[c*3+1];
            float p2 = L[c*3+2] * wn[c*3+2];
            int   bi = 0;
            float best = p0;
            if (p1 < best) { best = p1; bi = 1; }
            if (p2 < best) { best = p2; bi = 2; }
            float second = fmaxf(fminf(p0, p1), fminf(fmaxf(p0, p1), p2));
            // fast rel err <= ~2.4e-4; eps = 1e-3 (4x margin)
            need_exact |= (second < fmaf(best, 1e-3f, best));
            cf[c]  = bi;
            lcf[c] = lp[c*3 + bi];
        }

        if (need_exact) {
            // Bit-exact reference arithmetic: s = lp - log(-log(max(u, tiny)))
            #pragma unroll
            for (int c = 0; c < 2; c++) {
                int   bi   = 0;
                float best = -1e30f;
                #pragma unroll
                for (int a = 0; a < 3; a++) {
                    float uc = fmaxf(u[c*3+a], 1.17549435e-38f);
                    float s  = lp[c*3+a] - logf(-logf(uc));
                    if (s > best) { best = s; bi = a; }   // first-max tie rule
                }
                cf[c]  = bi;
                lcf[c] = lp[c*3 + bi];
            }
        }

        int card = cardv[e];                       // in {0,1}
        int u0i  = (card == 0) ? cf[0] : cf[1];
        u0p[e]   = (float)u0i;

        bool eq = (cf[0] == cf[1]);
        belp[e*2 + 0] = eq ? 0.5f : ((card == 0) ? 1.0f : 0.0f);
        belp[e*2 + 1] = eq ? 0.5f : ((card == 0) ? 0.0f : 1.0f);
        lcfp[e*2 + 0] = lcf[0];
        lcfp[e*2 + 1] = lcf[1];
    }

    // Vectorized stores: out = [u0(B) | beliefs(B,2) | log_cf(B,2)]
    *reinterpret_cast<float2*>(out + e0)                         = u0d;
    *reinterpret_cast<float4*>(out + BATCH + 2u * e0)            = belq;
    *reinterpret_cast<float4*>(out + 3 * (size_t)BATCH + 2u * e0) = lcfq;
}

extern "C" void kernel_launch(void* const* d_in, const int* in_sizes, int n_in,
                              void* d_out, int out_size) {
    const int*   cards = (const int*)d_in[0];     // cards_0: (B,) int32
    const float* W     = (const float*)d_in[1];   // (3,2) float32
    const float* bias  = (const float*)d_in[2];   // (3,) float32
    float*       out   = (float*)d_out;           // [u0(B) | beliefs(B,2) | log_cf(B,2)]

    init_logp_kernel<<<1, 32>>>(W, bias);
    sample_kernel<<<BATCH / (256 * EPT), 256>>>(cards, out);
}